// round 13
// baseline (speedup 1.0000x reference)
#include <cuda_runtime.h>
#include <cuda_fp16.h>
#include <cstdint>

#define GST   262144             // elems per (f,g) slab
#define NU_H  3584               // 14 mtiles * 8 ntiles * 32 ic
#define NU_F  512                // 2 mt * 4 nt * 32 ic * 2 gh
#define FBUF  16896              // FFMA buf bytes: 32*132*4
#define SMEM_BYTES (2*FBUF*2)    // 67584 (FFMA A + B, 2 bufs each)

__device__ __half g_fcH[26214400];  // [f][g][o][i], scaled by 256

__device__ __forceinline__ void cpa16(uint32_t s, const void* g){
    asm volatile("cp.async.cg.shared.global [%0], [%1], 16;" :: "r"(s), "l"(g));
}
__device__ __forceinline__ uint32_t ph2(float lo, float hi){
    __half2 h = __floats2half2_rn(lo, hi);
    return *reinterpret_cast<uint32_t*>(&h);
}
__device__ __forceinline__ void mma16(float* d, const uint4 a, uint32_t b0, uint32_t b1){
    asm volatile("mma.sync.aligned.m16n8k16.row.col.f32.f16.f16.f32 "
        "{%0,%1,%2,%3}, {%4,%5,%6,%7}, {%8,%9}, {%0,%1,%2,%3};"
        : "+f"(d[0]),"+f"(d[1]),"+f"(d[2]),"+f"(d[3])
        : "r"(a.x),"r"(a.y),"r"(a.z),"r"(a.w), "r"(b0),"r"(b1));
}
__device__ __forceinline__ unsigned long long pk2(float v){
    unsigned long long r; asm("mov.b64 %0, {%1, %1};" : "=l"(r) : "f"(v)); return r;
}
__device__ __forceinline__ float2 upk(unsigned long long v){
    float2 r; asm("mov.b64 {%0, %1}, %2;" : "=f"(r.x), "=f"(r.y) : "l"(v)); return r;
}
__device__ __forceinline__ void fma2(unsigned long long& d, unsigned long long a, unsigned long long b){
    asm("fma.rn.f32x2 %0, %1, %2, %0;" : "+l"(d) : "l"(a), "l"(b));
}

__global__ void init_out_kernel(const float* __restrict__ bias, float* __restrict__ out){
    int i = (blockIdx.x*256 + threadIdx.x)*4;
    *(float4*)(out + i) = *(const float4*)(bias + (i & 511));
}

// transpose fc[q][i][o] -> g_fcH[q][o][i] * 256, fp16
__global__ void __launch_bounds__(256) prep_kernel(const float* __restrict__ fc){
    __shared__ float t[32][33];
    int q = blockIdx.z, i0 = blockIdx.x*32, o0 = blockIdx.y*32;
    const float* src = fc + (size_t)q*GST;
    __half* dst = g_fcH + (size_t)q*GST;
    int tx = threadIdx.x, ty = threadIdx.y;
#pragma unroll
    for (int j=0;j<4;++j) t[ty+8*j][tx] = src[(size_t)(i0+ty+8*j)*512 + o0+tx];
    __syncthreads();
    int tid = ty*32+tx, o = tid>>3, s = tid&7;
    float v0 = t[s*4+0][o]*256.f, v1 = t[s*4+1][o]*256.f;
    float v2 = t[s*4+2][o]*256.f, v3 = t[s*4+3][o]*256.f;
    uint2 w = make_uint2(ph2(v0,v1), ph2(v2,v3));
    *(uint2*)(dst + (size_t)(o0+o)*512 + i0 + s*4) = w;
}

__global__ void __launch_bounds__(128,2)
fkan_dual(const float* __restrict__ x, const float* __restrict__ fc,
          float* __restrict__ out)
{
    extern __shared__ __align__(16) char smem[];
    const int tid  = threadIdx.x;
    const int lane = tid & 31;
    const int wid  = tid >> 5;

    if (blockIdx.x < 148) {
        // ================= HMMA path (round-12, rows 0..1791) =================
        uint4* Af  = (uint4*)smem;                       // [2][16][32]
        __half* Bs = (__half*)(smem + 16384);            // [2][64][40]
        const uint32_t bs_sa = (uint32_t)__cvta_generic_to_shared(Bs);

        const int gid = lane >> 2, tig = lane & 3;
        const int wm  = wid >> 1,  wn  = wid & 1;
        const int gb  = lane >> 2, ga = lane & 3;

        int cf_[2], cco[2], ccio[2]; uint32_t cdst[2];
#pragma unroll
        for (int q=0;q<2;++q){
            int cidx = q*128 + tid;
            cf_[q] = cidx>>7; cco[q] = (cidx>>1)&63; ccio[q] = cidx&1;
            cdst[q] = bs_sa + (uint32_t)(cco[q]*80 + cf_[q]*32 + ccio[q]*16);
        }

        const int c = blockIdx.x;
        const int u0 = (NU_H*c)/148, u1 = (NU_H*(c+1))/148;

        float acc[4][4][4];
#pragma unroll
        for (int a1=0;a1<4;++a1)
#pragma unroll
        for (int b1=0;b1<4;++b1)
#pragma unroll
        for (int d1=0;d1<4;++d1) acc[a1][b1][d1]=0.f;

        int cur_tile = -1, cm0 = 0, cn0 = 0;
        const float SC = 1.f/256.f;

        for (int u = u0; u < u1; ++u){
            const int tile = u >> 5, ic = u & 31;
            const int m0 = (tile>>3)*128, n0 = (tile&7)*64, ib = ic*16;

            if (tile != cur_tile){
                if (cur_tile >= 0){
#pragma unroll
                    for (int mt=0;mt<4;++mt)
#pragma unroll
                    for (int nt=0;nt<4;++nt){
                        float* op = out + (size_t)(cm0 + wm*64 + mt*16 + gid)*512 + cn0 + wn*32 + nt*8 + 2*tig;
                        atomicAdd(op,      acc[mt][nt][0]*SC);
                        atomicAdd(op+1,    acc[mt][nt][1]*SC);
                        atomicAdd(op+4096, acc[mt][nt][2]*SC);
                        atomicAdd(op+4097, acc[mt][nt][3]*SC);
                    }
#pragma unroll
                    for (int a1=0;a1<4;++a1)
#pragma unroll
                    for (int b1=0;b1<4;++b1)
#pragma unroll
                    for (int d1=0;d1<4;++d1) acc[a1][b1][d1]=0.f;
                }
                cur_tile = tile; cm0 = m0; cn0 = n0;
            }

            float ss[16], cc[16], s1[16], c1[16];
#pragma unroll
            for (int mq=0; mq<2; ++mq)
#pragma unroll
            for (int mh=0; mh<2; ++mh)
#pragma unroll
            for (int iv=0; iv<4; ++iv){
                int j = mq*8 + mh*4 + iv;
                int i = ib + 2*ga + (iv&1) + 8*(iv>>1);
                int m = m0 + (wid*2+mq)*16 + gb + 8*mh;
                float xv = __ldg(x + (size_t)m*512 + i);
                sincospif(xv, &s1[j], &c1[j]);
                ss[j]=s1[j]; cc[j]=c1[j];
            }

            const __half* gb0 = g_fcH + ((size_t)(cf_[0]*50)*512 + n0 + cco[0])*512 + ib + ccio[0]*8;
            const __half* gb1 = g_fcH + ((size_t)(cf_[1]*50)*512 + n0 + cco[1])*512 + ib + ccio[1]*8;

#pragma unroll
            for (int mq=0; mq<2; ++mq){
                int mtile = wid*2+mq, b = mq*8;
                Af[(mtile*2+0)*32 + lane] = make_uint4(ph2(ss[b+0],ss[b+1]), ph2(ss[b+4],ss[b+5]),
                                                       ph2(ss[b+2],ss[b+3]), ph2(ss[b+6],ss[b+7]));
                Af[(mtile*2+1)*32 + lane] = make_uint4(ph2(cc[b+0],cc[b+1]), ph2(cc[b+4],cc[b+5]),
                                                       ph2(cc[b+2],cc[b+3]), ph2(cc[b+6],cc[b+7]));
            }
            cpa16(cdst[0], gb0);
            cpa16(cdst[1], gb1);
            asm volatile("cp.async.commit_group;");

            for (int g=0; g<50; ++g){
                const int cur = g&1, nxt = cur^1;
                const bool hn = (g < 49);
                if (hn){
#pragma unroll
                    for (int j=0;j<16;++j){
                        float ns = fmaf(ss[j], c1[j],  cc[j]*s1[j]);
                        float nc = fmaf(cc[j], c1[j], -ss[j]*s1[j]);
                        ss[j]=ns; cc[j]=nc;
                    }
                }
                asm volatile("cp.async.wait_group 0;");
                __syncthreads();
                if (hn){
#pragma unroll
                    for (int mq=0; mq<2; ++mq){
                        int mtile = wid*2+mq, b = mq*8;
                        Af[(nxt*16 + mtile*2+0)*32 + lane] = make_uint4(ph2(ss[b+0],ss[b+1]), ph2(ss[b+4],ss[b+5]),
                                                                        ph2(ss[b+2],ss[b+3]), ph2(ss[b+6],ss[b+7]));
                        Af[(nxt*16 + mtile*2+1)*32 + lane] = make_uint4(ph2(cc[b+0],cc[b+1]), ph2(cc[b+4],cc[b+5]),
                                                                        ph2(cc[b+2],cc[b+3]), ph2(cc[b+6],cc[b+7]));
                    }
                    size_t go = (size_t)(g+1)*GST;
                    cpa16(cdst[0] + nxt*5120u, gb0 + go);
                    cpa16(cdst[1] + nxt*5120u, gb1 + go);
                    asm volatile("cp.async.commit_group;");
                }
#pragma unroll
                for (int kt=0; kt<2; ++kt){
                    uint4 av[4];
#pragma unroll
                    for (int mt=0;mt<4;++mt) av[mt] = Af[(cur*16 + (wm*4+mt)*2 + kt)*32 + lane];
#pragma unroll
                    for (int nt=0;nt<4;++nt){
                        const __half* bp = Bs + (size_t)cur*2560 + (wn*32 + nt*8 + gid)*40 + kt*16 + 2*tig;
                        uint32_t b0 = *(const uint32_t*)bp;
                        uint32_t b1 = *(const uint32_t*)(bp + 8);
#pragma unroll
                        for (int mt=0;mt<4;++mt) mma16(acc[mt][nt], av[mt], b0, b1);
                    }
                }
                __syncthreads();
            }
        }
        if (cur_tile >= 0){
#pragma unroll
            for (int mt=0;mt<4;++mt)
#pragma unroll
            for (int nt=0;nt<4;++nt){
                float* op = out + (size_t)(cm0 + wm*64 + mt*16 + gid)*512 + cn0 + wn*32 + nt*8 + 2*tig;
                atomicAdd(op,      acc[mt][nt][0]*SC);
                atomicAdd(op+1,    acc[mt][nt][1]*SC);
                atomicAdd(op+4096, acc[mt][nt][2]*SC);
                atomicAdd(op+4097, acc[mt][nt][3]*SC);
            }
        }
    } else {
        // ================= FFMA2 path (rows 1792..2047, fp32) =================
        float* As = (float*)smem;                 // [2][32][132]
        float* Bf = (float*)(smem + 2*FBUF);      // [2][32][132]
        const uint32_t b_sa = (uint32_t)__cvta_generic_to_shared(Bf);

        const int wm2 = wid>>1, wn2 = wid&1;
        const int tb  = wm2*64 + (lane>>3)*16;    // thread m-base in tile
        const int nb  = wn2*64 + (lane&7)*8;      // thread n-base in tile
        const int gii = tid & 15, gmo = (tid>>4)*16;

        // B fragment smem byte offsets (swizzled)
        const int c0 = (nb>>2), c1x = c0+1;
        const uint32_t bo0 = (uint32_t)((c0  ^ ((c0 >>3)&1))*16);
        const uint32_t bo1 = (uint32_t)((c1x ^ ((c1x>>3)&1))*16);

        // cp.async chunk map: 8 chunks of 16B per buffer per thread
        uint32_t bdst[8]; const float* bbase[8];
#pragma unroll
        for (int q=0;q<8;++q){
            int cidx = q*128 + tid, row = cidx>>5, col = cidx&31;
            int f = row>>4, ii = row&15;
            bdst[q]  = b_sa + (uint32_t)(row*528 + (col ^ ((col>>3)&1))*16);
            bbase[q] = fc + ((size_t)(f*50)*512 + ii)*512 + col*4;
        }

        const int cfc = blockIdx.x - 148;
        const int u0 = (NU_F*cfc)/148, u1 = (NU_F*(cfc+1))/148;

        unsigned long long acc[16][4];
#pragma unroll
        for (int r=0;r<16;++r)
#pragma unroll
        for (int p=0;p<4;++p) acc[r][p] = 0ull;

        int ctile = -1, cm = 0, cn = 0;

        for (int u = u0; u < u1; ++u){
            const int tile = u>>6, rem = u&63, ic = rem>>1, gh = rem&1;
            const int m0 = 1792 + (tile>>2)*128, n0 = (tile&3)*128, ib = ic*16;
            const int gs = gh*25;

            if (tile != ctile){
                if (ctile >= 0){
#pragma unroll
                    for (int r=0;r<16;++r)
#pragma unroll
                    for (int p=0;p<4;++p){
                        float2 v = upk(acc[r][p]);
                        float* op = out + (size_t)(cm + tb + r)*512 + cn + nb + 2*p;
                        atomicAdd(op,   v.x);
                        atomicAdd(op+1, v.y);
                        acc[r][p] = 0ull;
                    }
                }
                ctile = tile; cm = m0; cn = n0;
            }

            // init rotation states at k = gs+1
            float ss[16], cc[16], s1v[16], c1v[16];
            const float k0 = (float)(gs + 1);
#pragma unroll
            for (int r=0;r<16;++r){
                float xv = __ldg(x + (size_t)(m0 + gmo + r)*512 + ib + gii);
                sincospif(xv, &s1v[r], &c1v[r]);
                sincospif(k0*xv, &ss[r], &cc[r]);
            }

            // prologue: A buf0 + B(gs)
#pragma unroll
            for (int j=0;j<4;++j){
                *(float4*)&As[(0*16+gii)*132 + gmo + 4*j]  = *(float4*)&ss[4*j];
                *(float4*)&As[(1*16+gii)*132 + gmo + 4*j]  = *(float4*)&cc[4*j];
            }
#pragma unroll
            for (int q=0;q<8;++q)
                cpa16(bdst[q], bbase[q] + n0 + (size_t)gs*GST + (size_t)ib*512);
            asm volatile("cp.async.commit_group;");

            for (int gg=0; gg<25; ++gg){
                const int cur = gg&1, nxt = cur^1;
                const bool hn = (gg < 24);
                if (hn){
#pragma unroll
                    for (int r=0;r<16;++r){
                        float ns = fmaf(ss[r], c1v[r],  cc[r]*s1v[r]);
                        float nc = fmaf(cc[r], c1v[r], -ss[r]*s1v[r]);
                        ss[r]=ns; cc[r]=nc;
                    }
                }
                asm volatile("cp.async.wait_group 0;");
                __syncthreads();
                if (hn){
#pragma unroll
                    for (int j=0;j<4;++j){
                        *(float4*)&As[nxt*4224 + (0*16+gii)*132 + gmo + 4*j] = *(float4*)&ss[4*j];
                        *(float4*)&As[nxt*4224 + (1*16+gii)*132 + gmo + 4*j] = *(float4*)&cc[4*j];
                    }
                    size_t go = (size_t)(gs+gg+1)*GST + (size_t)ib*512 + n0;
#pragma unroll
                    for (int q=0;q<8;++q)
                        cpa16(bdst[q] + nxt*FBUF, bbase[q] + go);
                    asm volatile("cp.async.commit_group;");
                }
                // GEMM: 128m x 128n x 32k
                const float* ap = As + cur*4224;
                const char*  bp = (const char*)Bf + cur*FBUF;
#pragma unroll 4
                for (int kk=0; kk<32; ++kk){
                    float4 A0 = *(const float4*)(ap + kk*132 + tb);
                    float4 A1 = *(const float4*)(ap + kk*132 + tb + 4);
                    float4 A2 = *(const float4*)(ap + kk*132 + tb + 8);
                    float4 A3 = *(const float4*)(ap + kk*132 + tb + 12);
                    ulonglong2 U0 = *(const ulonglong2*)(bp + kk*528 + bo0);
                    ulonglong2 U1 = *(const ulonglong2*)(bp + kk*528 + bo1);
                    float a[16] = {A0.x,A0.y,A0.z,A0.w,A1.x,A1.y,A1.z,A1.w,
                                   A2.x,A2.y,A2.z,A2.w,A3.x,A3.y,A3.z,A3.w};
#pragma unroll
                    for (int r=0;r<16;++r){
                        unsigned long long ad = pk2(a[r]);
                        fma2(acc[r][0], ad, U0.x); fma2(acc[r][1], ad, U0.y);
                        fma2(acc[r][2], ad, U1.x); fma2(acc[r][3], ad, U1.y);
                    }
                }
                __syncthreads();
            }
        }
        if (ctile >= 0){
#pragma unroll
            for (int r=0;r<16;++r)
#pragma unroll
            for (int p=0;p<4;++p){
                float2 v = upk(acc[r][p]);
                float* op = out + (size_t)(cm + tb + r)*512 + cn + nb + 2*p;
                atomicAdd(op,   v.x);
                atomicAdd(op+1, v.y);
            }
        }
    }
}

extern "C" void kernel_launch(void* const* d_in, const int* in_sizes, int n_in,
                              void* d_out, int out_size) {
    const float* x    = (const float*)d_in[0];
    const float* fc   = (const float*)d_in[1];
    const float* bias = (const float*)d_in[2];
    float* out = (float*)d_out;

    cudaFuncSetAttribute(fkan_dual, cudaFuncAttributeMaxDynamicSharedMemorySize, SMEM_BYTES);

    init_out_kernel<<<1024, 256>>>(bias, out);
    prep_kernel<<<dim3(16,16,100), dim3(32,8)>>>(fc);
    fkan_dual<<<296, 128, SMEM_BYTES>>>(x, fc, out);
}

// round 14
// speedup vs baseline: 1.2892x; 1.2892x over previous
#include <cuda_runtime.h>
#include <cuda_fp16.h>
#include <cstdint>

#define NUNITS 4096
#define NCTAS  296
#define GST    262144              // fp32 elems per (f,g) slab of fc

__device__ __forceinline__ uint32_t ph2(float lo, float hi){
    __half2 h = __floats2half2_rn(lo, hi);
    return *reinterpret_cast<uint32_t*>(&h);
}
__device__ __forceinline__ void mma16(float* d, const uint4 a, uint32_t b0, uint32_t b1){
    asm volatile("mma.sync.aligned.m16n8k16.row.col.f32.f16.f16.f32 "
        "{%0,%1,%2,%3}, {%4,%5,%6,%7}, {%8,%9}, {%0,%1,%2,%3};"
        : "+f"(d[0]),"+f"(d[1]),"+f"(d[2]),"+f"(d[3])
        : "r"(a.x),"r"(a.y),"r"(a.z),"r"(a.w), "r"(b0),"r"(b1));
}

__global__ void init_out_kernel(const float* __restrict__ bias, float* __restrict__ out){
    int i = (blockIdx.x*256 + threadIdx.x)*4;
    *(float4*)(out + i) = *(const float4*)(bias + (i & 511));
}

__global__ void __launch_bounds__(128,2)
fkan_fp16(const float* __restrict__ x, const float* __restrict__ fc,
          float* __restrict__ out)
{
    __shared__ __align__(16) uint4 Af[2][16][32];   // A frags [buf][mtile*2+kt][lane]
    __shared__ __align__(16) char  Bh[2][4608];     // B fp16 [buf][k=32 rows x 144B (72h pitch)]

    const int tid  = threadIdx.x;
    const int lane = tid & 31;
    const int wid  = tid >> 5;           // 0..3
    const int gid  = lane >> 2, tig = lane & 3;
    const int wm   = wid >> 1,  wn  = wid & 1;
    const int gb   = lane >> 2, ga = lane & 3;

    // ---- converter constants: thread owns B row ck, chunks J = cq and cq+4 ----
    const int ck = tid >> 2, cq = tid & 3;
    const int ci = ck & 15;                          // i within chunk
    const size_t cslab = (size_t)(ck >> 4) * 50 * GST;  // sin rows -> slab 0, cos -> slab 50
    const int sw0 = (cq ^ (ck & 7)) * 16;
    const int cst0 = ck*144 + sw0;
    const int cst1 = ck*144 + (sw0 ^ 64);

    // ---- ldmatrix lane constants ----
    const int l7 = lane & 7;
    const uint32_t bh_sa = (uint32_t)__cvta_generic_to_shared(&Bh[0][0]);
    const uint32_t lrow0 = (uint32_t)((((lane>>3)&1)*8 + l7) * 144);
    const uint32_t lrow1 = lrow0 + 16*144;
    const int Jb = wn*4;

    const int c = blockIdx.x;
    const int u0 = (NUNITS*c)/NCTAS, u1 = (NUNITS*(c+1))/NCTAS;

    float acc[4][4][4];
#pragma unroll
    for (int a1=0;a1<4;++a1)
#pragma unroll
    for (int b1=0;b1<4;++b1)
#pragma unroll
    for (int d1=0;d1<4;++d1) acc[a1][b1][d1]=0.f;

    int cur_tile = -1, cm0 = 0, cn0 = 0;
    const float SC = 1.f/256.f, UP = 256.f;

    for (int u = u0; u < u1; ++u){
        const int tile = u >> 5, ic = u & 31;
        const int m0 = (tile>>3)*128, n0 = (tile&7)*64, ib = ic*16;

        if (tile != cur_tile){
            if (cur_tile >= 0){
#pragma unroll
                for (int mt=0;mt<4;++mt)
#pragma unroll
                for (int nt=0;nt<4;++nt){
                    float* op = out + (size_t)(cm0 + wm*64 + mt*16 + gid)*512 + cn0 + wn*32 + nt*8 + 2*tig;
                    atomicAdd(op,      acc[mt][nt][0]*SC);
                    atomicAdd(op+1,    acc[mt][nt][1]*SC);
                    atomicAdd(op+4096, acc[mt][nt][2]*SC);
                    atomicAdd(op+4097, acc[mt][nt][3]*SC);
                }
#pragma unroll
                for (int a1=0;a1<4;++a1)
#pragma unroll
                for (int b1=0;b1<4;++b1)
#pragma unroll
                for (int d1=0;d1<4;++d1) acc[a1][b1][d1]=0.f;
            }
            cur_tile = tile; cm0 = m0; cn0 = n0;
        }

        // ---- init rotation states (k=1): 16 states/thread over 2 mtiles ----
        float ss[16], cc[16], s1[16], c1[16];
#pragma unroll
        for (int mq=0; mq<2; ++mq)
#pragma unroll
        for (int mh=0; mh<2; ++mh)
#pragma unroll
        for (int iv=0; iv<4; ++iv){
            int j = mq*8 + mh*4 + iv;
            int i = ib + 2*ga + (iv&1) + 8*(iv>>1);
            int m = m0 + (wid*2+mq)*16 + gb + 8*mh;
            float xv = __ldg(x + (size_t)m*512 + i);
            sincospif(xv, &s1[j], &c1[j]);
            ss[j]=s1[j]; cc[j]=c1[j];
        }

        // converter fc pointer for this unit (g=0)
        const float* cfp = fc + cslab + (size_t)(ib + ci)*512 + n0 + 8*cq;

        // ---- prologue: Af[0] + Bh[0] (g=0) ----
#pragma unroll
        for (int mq=0; mq<2; ++mq){
            int mtile = wid*2+mq, b = mq*8;
            Af[0][mtile*2+0][lane] = make_uint4(ph2(ss[b+0],ss[b+1]), ph2(ss[b+4],ss[b+5]),
                                                ph2(ss[b+2],ss[b+3]), ph2(ss[b+6],ss[b+7]));
            Af[0][mtile*2+1][lane] = make_uint4(ph2(cc[b+0],cc[b+1]), ph2(cc[b+4],cc[b+5]),
                                                ph2(cc[b+2],cc[b+3]), ph2(cc[b+6],cc[b+7]));
        }
        {
            float4 v0 = *(const float4*)(cfp);
            float4 v1 = *(const float4*)(cfp + 4);
            float4 v2 = *(const float4*)(cfp + 32);
            float4 v3 = *(const float4*)(cfp + 36);
            uint4 h0 = make_uint4(ph2(v0.x*UP,v0.y*UP), ph2(v0.z*UP,v0.w*UP),
                                  ph2(v1.x*UP,v1.y*UP), ph2(v1.z*UP,v1.w*UP));
            uint4 h1 = make_uint4(ph2(v2.x*UP,v2.y*UP), ph2(v2.z*UP,v2.w*UP),
                                  ph2(v3.x*UP,v3.y*UP), ph2(v3.z*UP,v3.w*UP));
            *(uint4*)(&Bh[0][0] + cst0) = h0;
            *(uint4*)(&Bh[0][0] + cst1) = h1;
        }

        for (int g=0; g<50; ++g){
            const int cur = g&1, nxt = cur^1;
            __syncthreads();
            const bool hn = (g < 49);
            float4 v0, v1, v2, v3;
            if (hn){
                // issue next-g B loads early (L2-resident fc)
                const float* p = cfp + (size_t)(g+1)*GST;
                v0 = *(const float4*)(p);
                v1 = *(const float4*)(p + 4);
                v2 = *(const float4*)(p + 32);
                v3 = *(const float4*)(p + 36);
                // advance rotation states
#pragma unroll
                for (int j=0;j<16;++j){
                    float ns = fmaf(ss[j], c1[j],  cc[j]*s1[j]);
                    float nc = fmaf(cc[j], c1[j], -ss[j]*s1[j]);
                    ss[j]=ns; cc[j]=nc;
                }
            }
            // ---- GEMM: 128m x 64n x 32k (fp16 HMMA), warp = 64m x 32n ----
            const uint32_t bh_cur = bh_sa + (uint32_t)cur*4608u;
#pragma unroll
            for (int kt=0; kt<2; ++kt){
                uint4 av[4];
#pragma unroll
                for (int mt=0;mt<4;++mt) av[mt] = Af[cur][(wm*4+mt)*2 + kt][lane];
                const uint32_t lrow = kt ? lrow1 : lrow0;
#pragma unroll
                for (int nt=0;nt<4;++nt){
                    uint32_t ad = bh_cur + lrow + ((uint32_t)((Jb+nt) ^ l7) << 4);
                    uint32_t b0, b1;
                    asm volatile("ldmatrix.sync.aligned.m8n8.x2.trans.shared.b16 {%0,%1}, [%2];"
                                 : "=r"(b0), "=r"(b1) : "r"(ad));
#pragma unroll
                    for (int mt=0;mt<4;++mt) mma16(acc[mt][nt], av[mt], b0, b1);
                }
            }
            if (hn){
#pragma unroll
                for (int mq=0; mq<2; ++mq){
                    int mtile = wid*2+mq, b = mq*8;
                    Af[nxt][mtile*2+0][lane] = make_uint4(ph2(ss[b+0],ss[b+1]), ph2(ss[b+4],ss[b+5]),
                                                          ph2(ss[b+2],ss[b+3]), ph2(ss[b+6],ss[b+7]));
                    Af[nxt][mtile*2+1][lane] = make_uint4(ph2(cc[b+0],cc[b+1]), ph2(cc[b+4],cc[b+5]),
                                                          ph2(cc[b+2],cc[b+3]), ph2(cc[b+6],cc[b+7]));
                }
                uint4 h0 = make_uint4(ph2(v0.x*UP,v0.y*UP), ph2(v0.z*UP,v0.w*UP),
                                      ph2(v1.x*UP,v1.y*UP), ph2(v1.z*UP,v1.w*UP));
                uint4 h1 = make_uint4(ph2(v2.x*UP,v2.y*UP), ph2(v2.z*UP,v2.w*UP),
                                      ph2(v3.x*UP,v3.y*UP), ph2(v3.z*UP,v3.w*UP));
                *(uint4*)(&Bh[nxt][0] + cst0) = h0;
                *(uint4*)(&Bh[nxt][0] + cst1) = h1;
            }
        }
    }

    // final flush
    if (cur_tile >= 0){
#pragma unroll
        for (int mt=0;mt<4;++mt)
#pragma unroll
        for (int nt=0;nt<4;++nt){
            float* op = out + (size_t)(cm0 + wm*64 + mt*16 + gid)*512 + cn0 + wn*32 + nt*8 + 2*tig;
            atomicAdd(op,      acc[mt][nt][0]*SC);
            atomicAdd(op+1,    acc[mt][nt][1]*SC);
            atomicAdd(op+4096, acc[mt][nt][2]*SC);
            atomicAdd(op+4097, acc[mt][nt][3]*SC);
        }
    }
}

extern "C" void kernel_launch(void* const* d_in, const int* in_sizes, int n_in,
                              void* d_out, int out_size) {
    const float* x    = (const float*)d_in[0];
    const float* fc   = (const float*)d_in[1];
    const float* bias = (const float*)d_in[2];
    float* out = (float*)d_out;

    init_out_kernel<<<1024, 256>>>(bias, out);
    fkan_fp16<<<NCTAS, 128>>>(x, fc, out);
}

// round 16
// speedup vs baseline: 1.7488x; 1.3564x over previous
#include <cuda_runtime.h>
#include <cuda_fp16.h>
#include <cstdint>

#define NUNITS 4096
#define NCTAS  296
#define GST    262144              // elems per (f,g) slab

__device__ __half g_fcH[26214400];  // [f][g][o][i], scaled by 256

__device__ __forceinline__ void cpa16(uint32_t s, const void* g){
    asm volatile("cp.async.cg.shared.global [%0], [%1], 16;" :: "r"(s), "l"(g));
}
__device__ __forceinline__ uint32_t ph2(float lo, float hi){
    __half2 h = __floats2half2_rn(lo, hi);
    return *reinterpret_cast<uint32_t*>(&h);
}
__device__ __forceinline__ void mma16(float* d, const uint4 a, uint32_t b0, uint32_t b1){
    asm volatile("mma.sync.aligned.m16n8k16.row.col.f32.f16.f16.f32 "
        "{%0,%1,%2,%3}, {%4,%5,%6,%7}, {%8,%9}, {%0,%1,%2,%3};"
        : "+f"(d[0]),"+f"(d[1]),"+f"(d[2]),"+f"(d[3])
        : "r"(a.x),"r"(a.y),"r"(a.z),"r"(a.w), "r"(b0),"r"(b1));
}

// transpose fc[q][i][o] -> g_fcH[q][o][i] * 256 (fp16), and init out = bias.
// 64x64 tiles, 256 threads; grid (8, 8, 100). Row stride 68 floats = 272 B (16B aligned).
__global__ void __launch_bounds__(256) prep_kernel(const float* __restrict__ fc,
                                                   const float* __restrict__ bias,
                                                   float* __restrict__ out){
    __shared__ float t[64][68];
    const int q = blockIdx.z, i0 = blockIdx.x*64, o0 = blockIdx.y*64;
    const int tid = threadIdx.x;

    // fold in out-init: z-slice 0's 64 blocks cover 2048*512 floats
    if (q == 0){
        int blk = blockIdx.x*8 + blockIdx.y;
        float4 bv = *(const float4*)(bias + ((tid*4) & 511));
#pragma unroll
        for (int j=0;j<16;++j)
            *(float4*)(out + blk*16384 + j*1024 + tid*4) = bv;
    }

    const float* src = fc + (size_t)q*GST;
    __half* dst = g_fcH + (size_t)q*GST;

    const int r = tid >> 2, c16 = (tid & 3) * 16;
#pragma unroll
    for (int j=0;j<4;++j)
        *(float4*)&t[r][c16 + 4*j] = *(const float4*)(src + (size_t)(i0+r)*512 + o0 + c16 + 4*j);
    __syncthreads();

    const int orow = tid >> 2, i16 = (tid & 3) * 16;
    float v[16];
#pragma unroll
    for (int j=0;j<16;++j) v[j] = t[i16+j][orow] * 256.f;
    uint4 h0 = make_uint4(ph2(v[0],v[1]),  ph2(v[2],v[3]),  ph2(v[4],v[5]),  ph2(v[6],v[7]));
    uint4 h1 = make_uint4(ph2(v[8],v[9]),  ph2(v[10],v[11]),ph2(v[12],v[13]),ph2(v[14],v[15]));
    __half* dp = dst + (size_t)(o0+orow)*512 + i0 + i16;
    *(uint4*)(dp)     = h0;
    *(uint4*)(dp + 8) = h1;
}

__global__ void __launch_bounds__(128,2)
fkan_fp16(const float* __restrict__ x, float* __restrict__ out)
{
    __shared__ __align__(16) uint4  Af[2][16][32];     // [buf][mtile*2+kt][lane]
    __shared__ __align__(16) __half Bs[2][64][40];     // [buf][n][k], 8-half row pad

    const int tid  = threadIdx.x;
    const int lane = tid & 31;
    const int wid  = tid >> 5;           // 0..3
    const int gid  = lane >> 2, tig = lane & 3;
    const int wm   = wid >> 1,  wn  = wid & 1;
    const int gb   = lane >> 2, ga = lane & 3;

    // cp.async chunk mapping: 256 chunks of 16B per buffer, 2 per thread
    int cf[2], cco[2], ccio[2]; uint32_t cdst[2];
    const uint32_t bs_sa = (uint32_t)__cvta_generic_to_shared(&Bs[0][0][0]);
#pragma unroll
    for (int q=0;q<2;++q){
        int cidx = q*128 + tid;
        cf[q] = cidx>>7; cco[q] = (cidx>>1)&63; ccio[q] = cidx&1;
        cdst[q] = bs_sa + (uint32_t)(cco[q]*80 + cf[q]*32 + ccio[q]*16);
    }

    const int c = blockIdx.x;
    const int u0 = (NUNITS*c)/NCTAS, u1 = (NUNITS*(c+1))/NCTAS;

    float acc[4][4][4];
#pragma unroll
    for (int a1=0;a1<4;++a1)
#pragma unroll
    for (int b1=0;b1<4;++b1)
#pragma unroll
    for (int d1=0;d1<4;++d1) acc[a1][b1][d1]=0.f;

    int cur_tile = -1, cm0 = 0, cn0 = 0;
    const float SC = 1.f/256.f;

    for (int u = u0; u < u1; ++u){
        const int tile = u >> 5, ic = u & 31;
        const int m0 = (tile>>3)*128, n0 = (tile&7)*64, ib = ic*16;

        if (tile != cur_tile){
            if (cur_tile >= 0){
#pragma unroll
                for (int mt=0;mt<4;++mt)
#pragma unroll
                for (int nt=0;nt<4;++nt){
                    float* op = out + (size_t)(cm0 + wm*64 + mt*16 + gid)*512 + cn0 + wn*32 + nt*8 + 2*tig;
                    atomicAdd(op,      acc[mt][nt][0]*SC);
                    atomicAdd(op+1,    acc[mt][nt][1]*SC);
                    atomicAdd(op+4096, acc[mt][nt][2]*SC);
                    atomicAdd(op+4097, acc[mt][nt][3]*SC);
                }
#pragma unroll
                for (int a1=0;a1<4;++a1)
#pragma unroll
                for (int b1=0;b1<4;++b1)
#pragma unroll
                for (int d1=0;d1<4;++d1) acc[a1][b1][d1]=0.f;
            }
            cur_tile = tile; cm0 = m0; cn0 = n0;
        }

        // ---- init rotation states (k=1): 16 states/thread over 2 mtiles ----
        float ss[16], cc[16], s1[16], c1[16];
#pragma unroll
        for (int mq=0; mq<2; ++mq)
#pragma unroll
        for (int mh=0; mh<2; ++mh)
#pragma unroll
        for (int iv=0; iv<4; ++iv){
            int j = mq*8 + mh*4 + iv;
            int i = ib + 2*ga + (iv&1) + 8*(iv>>1);
            int m = m0 + (wid*2+mq)*16 + gb + 8*mh;
            float xv = __ldg(x + (size_t)m*512 + i);
            sincospif(xv, &s1[j], &c1[j]);
            ss[j]=s1[j]; cc[j]=c1[j];
        }

        const __half* gb0 = g_fcH + ((size_t)(cf[0]*50)*512 + n0 + cco[0])*512 + ib + ccio[0]*8;
        const __half* gb1 = g_fcH + ((size_t)(cf[1]*50)*512 + n0 + cco[1])*512 + ib + ccio[1]*8;

        // ---- prologue: Af[0] + B(g=0) ----
#pragma unroll
        for (int mq=0; mq<2; ++mq){
            int mtile = wid*2+mq, b = mq*8;
            Af[0][mtile*2+0][lane] = make_uint4(ph2(ss[b+0],ss[b+1]), ph2(ss[b+4],ss[b+5]),
                                                ph2(ss[b+2],ss[b+3]), ph2(ss[b+6],ss[b+7]));
            Af[0][mtile*2+1][lane] = make_uint4(ph2(cc[b+0],cc[b+1]), ph2(cc[b+4],cc[b+5]),
                                                ph2(cc[b+2],cc[b+3]), ph2(cc[b+6],cc[b+7]));
        }
        cpa16(cdst[0], gb0);
        cpa16(cdst[1], gb1);
        asm volatile("cp.async.commit_group;");

        for (int g=0; g<50; ++g){
            const int cur = g&1, nxt = cur^1;
            const bool hn = (g < 49);
            if (hn){
#pragma unroll
                for (int j=0;j<16;++j){
                    float ns = fmaf(ss[j], c1[j],  cc[j]*s1[j]);
                    float nc = fmaf(cc[j], c1[j], -ss[j]*s1[j]);
                    ss[j]=ns; cc[j]=nc;
                }
            }
            asm volatile("cp.async.wait_group 0;");
            __syncthreads();
            if (hn){
#pragma unroll
                for (int mq=0; mq<2; ++mq){
                    int mtile = wid*2+mq, b = mq*8;
                    Af[nxt][mtile*2+0][lane] = make_uint4(ph2(ss[b+0],ss[b+1]), ph2(ss[b+4],ss[b+5]),
                                                          ph2(ss[b+2],ss[b+3]), ph2(ss[b+6],ss[b+7]));
                    Af[nxt][mtile*2+1][lane] = make_uint4(ph2(cc[b+0],cc[b+1]), ph2(cc[b+4],cc[b+5]),
                                                          ph2(cc[b+2],cc[b+3]), ph2(cc[b+6],cc[b+7]));
                }
                size_t go = (size_t)(g+1)*GST;
                cpa16(cdst[0] + nxt*5120u, gb0 + go);
                cpa16(cdst[1] + nxt*5120u, gb1 + go);
                asm volatile("cp.async.commit_group;");
            }
            // ---- GEMM: 128m x 64n x 32k (fp16 HMMA), warp = 64m x 32n ----
#pragma unroll
            for (int kt=0; kt<2; ++kt){
                uint4 av[4];
#pragma unroll
                for (int mt=0;mt<4;++mt) av[mt] = Af[cur][(wm*4+mt)*2 + kt][lane];
#pragma unroll
                for (int nt=0;nt<4;++nt){
                    const __half* bp = &Bs[cur][wn*32 + nt*8 + gid][kt*16 + 2*tig];
                    uint32_t b0 = *(const uint32_t*)bp;
                    uint32_t b1 = *(const uint32_t*)(bp + 8);
#pragma unroll
                    for (int mt=0;mt<4;++mt) mma16(acc[mt][nt], av[mt], b0, b1);
                }
            }
            __syncthreads();
        }
    }

    // final flush
    if (cur_tile >= 0){
#pragma unroll
        for (int mt=0;mt<4;++mt)
#pragma unroll
        for (int nt=0;nt<4;++nt){
            float* op = out + (size_t)(cm0 + wm*64 + mt*16 + gid)*512 + cn0 + wn*32 + nt*8 + 2*tig;
            atomicAdd(op,      acc[mt][nt][0]*SC);
            atomicAdd(op+1,    acc[mt][nt][1]*SC);
            atomicAdd(op+4096, acc[mt][nt][2]*SC);
            atomicAdd(op+4097, acc[mt][nt][3]*SC);
        }
    }
}

extern "C" void kernel_launch(void* const* d_in, const int* in_sizes, int n_in,
                              void* d_out, int out_size) {
    const float* x    = (const float*)d_in[0];
    const float* fc   = (const float*)d_in[1];
    const float* bias = (const float*)d_in[2];
    float* out = (float*)d_out;

    prep_kernel<<<dim3(8,8,100), 256>>>(fc, bias, out);
    fkan_fp16<<<NCTAS, 128>>>(x, out);
}